// round 10
// baseline (speedup 1.0000x reference)
#include <cuda_runtime.h>
#include <math.h>
#include <float.h>

#define TT 8
#define NN 512
#define EE 64
#define HH 128
#define NC 16          // G*G
#define PP 128
#define KX 192         // E + P
#define KG 320         // KX + H
#define KSP 8          // K-splits for soc GEMM
#define NBLK 128

// ---------------- packed f32x2 helpers ----------------
__device__ __forceinline__ unsigned long long ffma2(unsigned long long a,
                                                    unsigned long long b,
                                                    unsigned long long c) {
    unsigned long long d;
    asm("fma.rn.f32x2 %0, %1, %2, %3;" : "=l"(d) : "l"(a), "l"(b), "l"(c));
    return d;
}
__device__ __forceinline__ unsigned long long pack2(float x, float y) {
    unsigned long long d;
    asm("mov.b64 %0, {%1, %2};" : "=l"(d) : "f"(x), "f"(y));
    return d;
}
__device__ __forceinline__ float2 upk(unsigned long long v) {
    float2 f;
    asm("mov.b64 {%0, %1}, %2;" : "=f"(f.x), "=f"(f.y) : "l"(v));
    return f;
}

// ---------------- persistent scratch ----------------
__device__ float g_obs[TT * NN * 2];
__device__ float g_h[2][NN * HH];
__device__ float g_c[NN * HH];
__device__ float g_grid[NN * NC * HH];
__device__ float g_part[KSP][NN * PP];
__device__ float g_slot[2][NN * 2];
__device__ unsigned g_count = 0;
__device__ unsigned g_gen = 0;

// ---------------- grid barrier (all NBLK blocks resident) ----------------
__device__ __forceinline__ void gridbar() {
    __threadfence();
    __syncthreads();
    if (threadIdx.x == 0) {
        volatile unsigned* genp = &g_gen;
        unsigned mygen = *genp;
        unsigned old = atomicAdd(&g_count, 1u);
        if (old == NBLK - 1u) {
            atomicExch(&g_count, 0u);
            __threadfence();
            *genp = mygen + 1u;
        } else {
            while (*genp == mygen) { }
        }
    }
    __syncthreads();
}

// dynamic smem: P needs 71680 B (max of phases)
#define SMEM_DYN 71680

__global__ void __launch_bounds__(256, 1) persist(
    const float* __restrict__ obs_in,
    const float* __restrict__ Wpos, const float* __restrict__ bpos,
    const float* __restrict__ Wpool, const float* __restrict__ bpool,
    const float* __restrict__ Wihe, const float* __restrict__ bihe,
    const float* __restrict__ Whhe, const float* __restrict__ bhhe,
    const float* __restrict__ Wihd, const float* __restrict__ bihd,
    const float* __restrict__ Whhd, const float* __restrict__ bhhd,
    const float* __restrict__ Wout, const float* __restrict__ bout,
    float* __restrict__ out, int np)
{
    extern __shared__ __align__(16) char smraw[];
    int tid = threadIdx.x;
    int vb  = blockIdx.x;

    // ================= SETUP: zero state + impute + slot init =================
    {
        int gid = vb * 256 + tid;
        for (int i = gid; i < NN * HH; i += NBLK * 256) {
            g_h[0][i] = 0.f; g_h[1][i] = 0.f; g_c[i] = 0.f;
        }
        if (gid < NN) {
            int n = gid;
            unsigned fm = 0; int first = 0; int ffound = 0;
            for (int t = 0; t < TT; t++) {
                float x = obs_in[(t * NN + n) * 2];
                float y = obs_in[(t * NN + n) * 2 + 1];
                if (isfinite(x) && isfinite(y)) {
                    fm |= (1u << t);
                    if (!ffound) { first = t; ffound = 1; }
                }
            }
            int last = -1;
            for (int t = 0; t < TT; t++) {
                if (fm & (1u << t)) last = t;
                int take = (last >= 0) ? last : first;
                float wx = 0.f, wy = 0.f;
                if (fm) {
                    wx = obs_in[(take * NN + n) * 2];
                    wy = obs_in[(take * NN + n) * 2 + 1];
                }
                g_obs[(t * NN + n) * 2]     = wx;
                g_obs[(t * NN + n) * 2 + 1] = wy;
            }
            float sx = g_obs[((TT - 1) * NN + n) * 2];
            float sy = g_obs[((TT - 1) * NN + n) * 2 + 1];
            g_slot[0][n * 2] = sx; g_slot[0][n * 2 + 1] = sy;
            g_slot[1][n * 2] = sx; g_slot[1][n * 2 + 1] = sy;
        }
    }
    gridbar();

    // ================= STEP LOOP =================
    int nsteps = (TT - 1) + np;
    for (int q = 0; q < nsteps; q++) {
        int dec = (q >= TT - 1);
        int s   = q - (TT - 1);
        int hb  = q & 1;
        const float* pos  = dec ? g_slot[s & 1]       : (g_obs + (q + 1) * NN * 2);
        const float* prev = dec ? g_slot[(s + 1) & 1] : (g_obs + q * NN * 2);
        const float* W_ih = dec ? Wihd : Wihe;
        const float* b_ih = dec ? bihd : bihe;
        const float* W_hh = dec ? Whhd : Whhe;
        const float* b_hh = dec ? bhhd : bhhe;
        const float* h_in = g_h[hb];
        float*       h_out = g_h[hb ^ 1];

        // ---------- Phase P: social pooling (4 agents/block) ----------
        {
            float* spos = (float*)smraw;                               // 1024 f
            unsigned char* scid = (unsigned char*)(smraw + 4096);      // 2048 B
            float* htile = (float*)(smraw + 6144);                     // 64*128 f
            float* sg    = (float*)(smraw + 6144 + 32768);             // 4*2048 f

            int base = vb * 4;
            int ch = tid & 127, apair = tid >> 7;

            for (int i = tid; i < NN * 2; i += 256) spos[i] = __ldcg(&pos[i]);
            for (int i = tid; i < 4 * NC * HH; i += 256) sg[i] = -FLT_MAX;
            __syncthreads();

            for (int it = tid; it < NN * 4; it += 256) {
                int a = it & 3, j = it >> 2;
                int i = base + a;
                float rx = spos[j * 2]     - spos[i * 2];
                float ry = spos[j * 2 + 1] - spos[i * 2 + 1];
                unsigned char cid = 255;
                if (j != i && fabsf(rx) <= 1.0f && fabsf(ry) <= 1.0f) {
                    int gx = (int)floorf((rx + 1.0f) * 2.0f);
                    int gy = (int)floorf((ry + 1.0f) * 2.0f);
                    gx = min(max(gx, 0), 3); gy = min(max(gy, 0), 3);
                    cid = (unsigned char)(gx * 4 + gy);
                }
                scid[j * 4 + a] = cid;
            }
            __syncthreads();

            const uchar4* sc4 = (const uchar4*)scid;
            for (int jt = 0; jt < NN; jt += 64) {
                for (int i = tid; i < 64 * HH; i += 256) {
                    int jl = i >> 7, cl = i & 127;
                    htile[i] = __ldcg(&h_in[(jt + jl) * HH + cl]);
                }
                __syncthreads();
                #pragma unroll 8
                for (int jl = 0; jl < 64; jl++) {
                    uchar4 c4 = sc4[jt + jl];
                    float hv = htile[jl * 128 + ch];
                    unsigned char ca = apair ? c4.z : c4.x;
                    unsigned char cb = apair ? c4.w : c4.y;
                    int a0 = apair * 2;
                    if (ca != 255) { float* p = &sg[a0 * 2048 + ca * 128 + ch]; *p = fmaxf(*p, hv); }
                    if (cb != 255) { float* p = &sg[(a0 + 1) * 2048 + cb * 128 + ch]; *p = fmaxf(*p, hv); }
                }
                __syncthreads();
            }
            for (int i = tid; i < 4 * NC * HH; i += 256) {
                float v = sg[i];
                __stcg(&g_grid[base * (NC * HH) + i], (v == -FLT_MAX) ? 0.f : v);
            }
        }
        gridbar();

        // ---------- Phase G: soc GEMM partials (64x64 tile, 8 K-splits) ----------
        {
            float* sA = (float*)smraw;            // [2][64][36]
            float* sB = (float*)(smraw + 18432);  // [2][32][64]

            int A0  = (vb & 7) * 64;
            int C0  = ((vb >> 3) & 1) * 64;
            int KB0 = (vb >> 4) * 256;

            int la  = tid >> 2, lka = (tid & 3) * 8;
            int cb  = tid & 63, lkb = (tid >> 6) * 8;
            const float* Asrc = &g_grid[(A0 + la) * (NC * HH) + KB0 + lka];
            const float* Bsrc = &Wpool[(C0 + cb) * (NC * HH) + KB0 + lkb];

            int a0 = (tid >> 4) * 4;
            int c0 = (tid & 15) * 4;

            float4 ra0, ra1, rb0, rb1;
#define G_LD(c) { const float* sa_ = Asrc + (c) * 32; const float* sb_ = Bsrc + (c) * 32; \
    ra0 = __ldcg((const float4*)sa_); ra1 = __ldcg((const float4*)sa_ + 1); \
    rb0 = ((const float4*)sb_)[0]; rb1 = ((const float4*)sb_)[1]; }
#define G_ST(buf) { \
    float* a_ = sA + (buf) * 2304 + la * 36 + lka; \
    ((float4*)a_)[0] = ra0; ((float4*)a_)[1] = ra1; \
    float* b_ = sB + (buf) * 2048 + lkb * 64 + cb; \
    b_[0*64] = rb0.x; b_[1*64] = rb0.y; b_[2*64] = rb0.z; b_[3*64] = rb0.w; \
    b_[4*64] = rb1.x; b_[5*64] = rb1.y; b_[6*64] = rb1.z; b_[7*64] = rb1.w; }

            G_LD(0); G_ST(0); G_LD(1);
            __syncthreads();

            unsigned long long acc[4][2] = {{0ull,0ull},{0ull,0ull},{0ull,0ull},{0ull,0ull}};
            for (int kc = 0; kc < 8; kc++) {
                int cur = kc & 1;
                if (kc + 1 < 8) G_ST(cur ^ 1);
                if (kc + 2 < 8) G_LD(kc + 2);
                #pragma unroll
                for (int k = 0; k < 32; k++) {
                    ulonglong2 bv = *(const ulonglong2*)&sB[cur * 2048 + k * 64 + c0];
                    float x0 = sA[cur * 2304 + (a0 + 0) * 36 + k];
                    float x1 = sA[cur * 2304 + (a0 + 1) * 36 + k];
                    float x2 = sA[cur * 2304 + (a0 + 2) * 36 + k];
                    float x3 = sA[cur * 2304 + (a0 + 3) * 36 + k];
                    unsigned long long xp;
                    xp = pack2(x0, x0); acc[0][0] = ffma2(xp, bv.x, acc[0][0]); acc[0][1] = ffma2(xp, bv.y, acc[0][1]);
                    xp = pack2(x1, x1); acc[1][0] = ffma2(xp, bv.x, acc[1][0]); acc[1][1] = ffma2(xp, bv.y, acc[1][1]);
                    xp = pack2(x2, x2); acc[2][0] = ffma2(xp, bv.x, acc[2][0]); acc[2][1] = ffma2(xp, bv.y, acc[2][1]);
                    xp = pack2(x3, x3); acc[3][0] = ffma2(xp, bv.x, acc[3][0]); acc[3][1] = ffma2(xp, bv.y, acc[3][1]);
                }
                __syncthreads();
            }
#undef G_LD
#undef G_ST
            float* dst = g_part[vb >> 4];
            #pragma unroll
            for (int i = 0; i < 4; i++) {
                __stcg((float2*)&dst[(A0 + a0 + i) * PP + C0 + c0],     upk(acc[i][0]));
                __stcg((float2*)&dst[(A0 + a0 + i) * PP + C0 + c0 + 2], upk(acc[i][1]));
            }
        }
        gridbar();

        // ---------- Phase L: x-build + gate GEMM + LSTM pointwise ----------
        {
            float* sX  = (float*)smraw;                  // [KG][16]
            float* sBW = (float*)(smraw + KG * 16 * 4);  // [2][2][8][128]

            int A0 = (vb >> 2) * 16;
            int h0 = (vb & 3) * 32;

            for (int it = tid; it < 16 * KG; it += 256) {
                int a = it / KG, k = it - a * KG;
                int ga = A0 + a;
                float v;
                if (k < EE) {
                    float vx = __ldcg(&pos[ga * 2])     - __ldcg(&prev[ga * 2]);
                    float vy = __ldcg(&pos[ga * 2 + 1]) - __ldcg(&prev[ga * 2 + 1]);
                    v = fmaxf(Wpos[k * 2] * vx + Wpos[k * 2 + 1] * vy + bpos[k], 0.f);
                } else if (k < KX) {
                    int c = k - EE;
                    float sum = bpool[c];
                    #pragma unroll
                    for (int p = 0; p < KSP; p++) sum += __ldcg(&g_part[p][ga * PP + c]);
                    v = fmaxf(sum, 0.f);
                } else {
                    v = __ldcg(&h_in[ga * HH + (k - KX)]);
                }
                sX[k * 16 + a] = v;
            }

            int kg = tid >> 7;
            int rr = tid & 127;
            int grow = h0 + (rr & 31) + ((rr >> 5) * HH);
            const float* ihrow = W_ih + grow * KX;
            const float* hhrow = W_hh + grow * HH;

            float4 w0, w1;
#define L_LD(c) { int kb_ = kg * 160 + (c) * 8; \
    const float* s_ = (kb_ < KX) ? (ihrow + kb_) : (hhrow + (kb_ - KX)); \
    w0 = ((const float4*)s_)[0]; w1 = ((const float4*)s_)[1]; }
#define L_ST(buf) { float* b_ = sBW + ((buf) * 2 + kg) * 1024 + rr; \
    b_[0*128] = w0.x; b_[1*128] = w0.y; b_[2*128] = w0.z; b_[3*128] = w0.w; \
    b_[4*128] = w1.x; b_[5*128] = w1.y; b_[6*128] = w1.z; b_[7*128] = w1.w; }

            L_LD(0); L_ST(0); L_LD(1);
            __syncthreads();

            int t  = tid & 127;
            int ag = t >> 5, rg = t & 31;
            int a0 = ag * 4, r0 = rg * 4;
            unsigned long long acc[4][2] = {{0ull,0ull},{0ull,0ull},{0ull,0ull},{0ull,0ull}};

            for (int kc = 0; kc < 20; kc++) {
                int cur = kc & 1;
                if (kc + 1 < 20) L_ST(cur ^ 1);
                if (kc + 2 < 20) L_LD(kc + 2);
                int kb = kg * 160 + kc * 8;
                #pragma unroll
                for (int k = 0; k < 8; k++) {
                    float4 xv = *(const float4*)&sX[(kb + k) * 16 + a0];
                    ulonglong2 wv = *(const ulonglong2*)&sBW[(cur * 2 + kg) * 1024 + k * 128 + r0];
                    unsigned long long xp;
                    xp = pack2(xv.x, xv.x); acc[0][0] = ffma2(xp, wv.x, acc[0][0]); acc[0][1] = ffma2(xp, wv.y, acc[0][1]);
                    xp = pack2(xv.y, xv.y); acc[1][0] = ffma2(xp, wv.x, acc[1][0]); acc[1][1] = ffma2(xp, wv.y, acc[1][1]);
                    xp = pack2(xv.z, xv.z); acc[2][0] = ffma2(xp, wv.x, acc[2][0]); acc[2][1] = ffma2(xp, wv.y, acc[2][1]);
                    xp = pack2(xv.w, xv.w); acc[3][0] = ffma2(xp, wv.x, acc[3][0]); acc[3][1] = ffma2(xp, wv.y, acc[3][1]);
                }
                __syncthreads();
            }
#undef L_LD
#undef L_ST

            // cross-group reduce + bias + gate staging (alias dead sX region)
            float* sRed = sX;            // [16][128]
            float* sG   = sX + 2048;     // [16][132]

            if (kg == 1) {
                #pragma unroll
                for (int i = 0; i < 4; i++) {
                    *(unsigned long long*)&sRed[(a0 + i) * 128 + r0]     = acc[i][0];
                    *(unsigned long long*)&sRed[(a0 + i) * 128 + r0 + 2] = acc[i][1];
                }
            }
            __syncthreads();
            if (kg == 0) {
                #pragma unroll
                for (int i = 0; i < 4; i++) {
                    float2 pa = upk(acc[i][0]), pb = upk(acc[i][1]);
                    float2 qa = *(float2*)&sRed[(a0 + i) * 128 + r0];
                    float2 qb = *(float2*)&sRed[(a0 + i) * 128 + r0 + 2];
                    float v[4] = {pa.x + qa.x, pa.y + qa.y, pb.x + qb.x, pb.y + qb.y};
                    #pragma unroll
                    for (int j = 0; j < 4; j++) {
                        int r = r0 + j;
                        int gr = h0 + (r & 31) + ((r >> 5) * HH);
                        sG[(a0 + i) * 132 + r] = v[j] + b_ih[gr] + b_hh[gr];
                    }
                }
            }
            __syncthreads();

            int hc = tid & 31;
            #pragma unroll
            for (int qq = 0; qq < 2; qq++) {
                int a  = (tid >> 5) + qq * 8;
                int ga = A0 + a;
                float iv = sG[a * 132 + hc],      fv = sG[a * 132 + 32 + hc];
                float gv = sG[a * 132 + 64 + hc], ov = sG[a * 132 + 96 + hc];
                int idx = ga * HH + h0 + hc;
                float c_old = g_c[idx];
                float si = 1.f / (1.f + __expf(-iv));
                float sf = 1.f / (1.f + __expf(-fv));
                float so = 1.f / (1.f + __expf(-ov));
                float cn = sf * c_old + si * tanhf(gv);
                float hn = so * tanhf(cn);
                g_c[idx] = cn;
                __stcg(&h_out[idx], hn);
            }
        }
        gridbar();

        // ---------- Phase O: decoder output projection + position advance ----------
        if (dec) {
            if (vb < 4) {
                int gid = vb * 256 + tid;
                int agent = gid >> 1, coord = gid & 1;
                const float* pos_cur = g_slot[s & 1];
                float* slot_next = g_slot[(s + 1) & 1];
                const float4* h4 = (const float4*)&h_out[agent * HH];
                const float4* w4 = (const float4*)&Wout[coord * HH];
                float acc = 0.f;
                #pragma unroll
                for (int k = 0; k < HH / 4; k++) {
                    float4 a = __ldcg(h4 + k);
                    float4 b = w4[k];
                    acc += a.x * b.x + a.y * b.y + a.z * b.z + a.w * b.w;
                }
                float v = __ldcg(&pos_cur[agent * 2 + coord]) + acc + bout[coord];
                __stcg(&slot_next[agent * 2 + coord], v);
                out[(s * NN + agent) * 2 + coord] = v;
            }
            gridbar();
        }
    }
}

// ---------------- host launcher ----------------
extern "C" void kernel_launch(void* const* d_in, const int* in_sizes, int n_in,
                              void* d_out, int out_size) {
    const float* obs   = (const float*)d_in[0];
    const float* Wposw = (const float*)d_in[1];
    const float* bposw = (const float*)d_in[2];
    const float* Wpool = (const float*)d_in[3];
    const float* bpool = (const float*)d_in[4];
    const float* Wihe  = (const float*)d_in[5];
    const float* bihe  = (const float*)d_in[6];
    const float* Whhe  = (const float*)d_in[7];
    const float* bhhe  = (const float*)d_in[8];
    const float* Wihd  = (const float*)d_in[9];
    const float* bihd  = (const float*)d_in[10];
    const float* Whhd  = (const float*)d_in[11];
    const float* bhhd  = (const float*)d_in[12];
    const float* Woutw = (const float*)d_in[13];
    const float* boutw = (const float*)d_in[14];
    float* out = (float*)d_out;
    int np = out_size / (NN * 2);

    cudaFuncSetAttribute(persist, cudaFuncAttributeMaxDynamicSharedMemorySize, SMEM_DYN);
    persist<<<NBLK, 256, SMEM_DYN>>>(obs, Wposw, bposw, Wpool, bpool,
                                     Wihe, bihe, Whhe, bhhe,
                                     Wihd, bihd, Whhd, bhhd,
                                     Woutw, boutw, out, np);
    (void)in_sizes; (void)n_in;
}

// round 14
// speedup vs baseline: 1.3003x; 1.3003x over previous
#include <cuda_runtime.h>
#include <math.h>
#include <float.h>

#define TT 8
#define NN 512
#define EE 64
#define HH 128
#define NC 16          // G*G
#define PP 128
#define KX 192         // E + P
#define KG 320         // KX + H
#define KSP 16         // K-splits for soc GEMM

// ---------------- packed f32x2 helpers ----------------
__device__ __forceinline__ unsigned long long ffma2(unsigned long long a,
                                                    unsigned long long b,
                                                    unsigned long long c) {
    unsigned long long d;
    asm("fma.rn.f32x2 %0, %1, %2, %3;" : "=l"(d) : "l"(a), "l"(b), "l"(c));
    return d;
}
__device__ __forceinline__ unsigned long long pack2(float x, float y) {
    unsigned long long d;
    asm("mov.b64 %0, {%1, %2};" : "=l"(d) : "f"(x), "f"(y));
    return d;
}
__device__ __forceinline__ float2 upk(unsigned long long v) {
    float2 f;
    asm("mov.b64 {%0, %1}, %2;" : "=f"(f.x), "=f"(f.y) : "l"(v));
    return f;
}

// ---------------- persistent scratch ----------------
__device__ float g_obs[TT * NN * 2];
__device__ float g_h[2][NN * HH];
__device__ float g_c[NN * HH];
__device__ float g_grid[NN * NC * HH];
__device__ float g_part[KSP][NN * PP];
__device__ float g_slot[2][NN * 2];

// ---------------- K0: impute + zero state ----------------
__global__ void k0_setup(const float* __restrict__ obs_in) {
    int gid = blockIdx.x * blockDim.x + threadIdx.x;
    int nth = gridDim.x * blockDim.x;
    for (int i = gid; i < NN * HH; i += nth) {
        g_h[0][i] = 0.f; g_h[1][i] = 0.f; g_c[i] = 0.f;
    }
    if (gid < NN) {
        int n = gid;
        unsigned fm = 0; int first = 0; int ffound = 0;
        for (int t = 0; t < TT; t++) {
            float x = obs_in[(t * NN + n) * 2];
            float y = obs_in[(t * NN + n) * 2 + 1];
            if (isfinite(x) && isfinite(y)) {
                fm |= (1u << t);
                if (!ffound) { first = t; ffound = 1; }
            }
        }
        int last = -1;
        for (int t = 0; t < TT; t++) {
            if (fm & (1u << t)) last = t;
            int take = (last >= 0) ? last : first;
            float wx = 0.f, wy = 0.f;
            if (fm) {
                wx = obs_in[(take * NN + n) * 2];
                wy = obs_in[(take * NN + n) * 2 + 1];
            }
            g_obs[(t * NN + n) * 2]     = wx;
            g_obs[(t * NN + n) * 2 + 1] = wy;
        }
        float sx = g_obs[((TT - 1) * NN + n) * 2];
        float sy = g_obs[((TT - 1) * NN + n) * 2 + 1];
        g_slot[0][n * 2] = sx; g_slot[0][n * 2 + 1] = sy;
        g_slot[1][n * 2] = sx; g_slot[1][n * 2 + 1] = sy;
    }
}

// ---------------- K1: social pooling, channel-split ----------------
// grid(16 agent-groups, 16 ch-groups) x 256 thr; 32 agents x 8 channels per block.
// L2 traffic for h: 512j x 8ch x 4B = 16KB/block -> 4MB/step total.
__global__ void __launch_bounds__(256) k1_pool(int hbuf, int pos_is_slot, int pos_idx) {
    __shared__ float spos[NN * 2];                 // 4KB
    __shared__ unsigned char scid[32 * NN];        // 16KB, [a][j]
    __shared__ float htile[64 * 8];                // 2KB
    __shared__ float sg[32 * 136];                 // 17.4KB, [a]*136 + cid*8 + ch

    const float* __restrict__ h_in = g_h[hbuf];
    const float* __restrict__ pos  = pos_is_slot ? g_slot[pos_idx] : (g_obs + pos_idx * NN * 2);

    int tid  = threadIdx.x;
    int base = blockIdx.x * 32;
    int ch0  = blockIdx.y * 8;

    for (int i = tid; i < NN * 2; i += 256) spos[i] = pos[i];
    for (int i = tid; i < 32 * 136; i += 256) sg[i] = -FLT_MAX;
    __syncthreads();

    // cell ids: scid[a*512 + j]
    for (int it = tid; it < 32 * NN; it += 256) {
        int a = it >> 9, j = it & (NN - 1);
        int i = base + a;
        float rx = spos[j * 2]     - spos[i * 2];
        float ry = spos[j * 2 + 1] - spos[i * 2 + 1];
        unsigned char cid = 255;
        if (j != i && fabsf(rx) <= 1.0f && fabsf(ry) <= 1.0f) {
            int gx = (int)floorf((rx + 1.0f) * 2.0f);
            int gy = (int)floorf((ry + 1.0f) * 2.0f);
            gx = min(max(gx, 0), 3); gy = min(max(gy, 0), 3);
            cid = (unsigned char)(gx * 4 + gy);
        }
        scid[it] = cid;
    }

    int a  = tid >> 3;          // 0..31
    int ch = tid & 7;           // 0..7
    float* sga = &sg[a * 136];
    const unsigned char* sca = &scid[a * NN];

    for (int jt = 0; jt < NN; jt += 64) {
        __syncthreads();
        for (int i = tid; i < 512; i += 256) {
            int jl = i >> 3, c = i & 7;
            htile[i] = h_in[(jt + jl) * HH + ch0 + c];
        }
        __syncthreads();
        #pragma unroll 4
        for (int j4 = 0; j4 < 16; j4++) {
            uchar4 c4 = *(const uchar4*)&sca[jt + j4 * 4];
            float h0v = htile[(j4 * 4 + 0) * 8 + ch];
            float h1v = htile[(j4 * 4 + 1) * 8 + ch];
            float h2v = htile[(j4 * 4 + 2) * 8 + ch];
            float h3v = htile[(j4 * 4 + 3) * 8 + ch];
            if (c4.x != 255) { float* p = &sga[c4.x * 8 + ch]; *p = fmaxf(*p, h0v); }
            if (c4.y != 255) { float* p = &sga[c4.y * 8 + ch]; *p = fmaxf(*p, h1v); }
            if (c4.z != 255) { float* p = &sga[c4.z * 8 + ch]; *p = fmaxf(*p, h2v); }
            if (c4.w != 255) { float* p = &sga[c4.w * 8 + ch]; *p = fmaxf(*p, h3v); }
        }
    }
    __syncthreads();

    // export: 32 agents x 16 cells x 8 ch
    for (int it = tid; it < 32 * 128; it += 256) {
        int aa = it >> 7, rest = it & 127;
        int cell = rest >> 3, c = rest & 7;
        float v = sg[aa * 136 + cell * 8 + c];
        g_grid[(base + aa) * (NC * HH) + cell * HH + ch0 + c] = (v == -FLT_MAX) ? 0.f : v;
    }
}

// ---------------- K2: soc GEMM partials: grid[512,2048] @ W_pool^T ----------------
// grid(8 M, 2 N, 16 Ksplit) = 256 blocks x 256 thr; tile 64x64, K=128/split.
__global__ void __launch_bounds__(256) k2_soc(const float* __restrict__ Wp) {
    __shared__ __align__(16) float sA[2][64][36];
    __shared__ __align__(16) float sB[2][32][64];

    int tid = threadIdx.x;
    int A0  = blockIdx.x * 64;
    int C0  = blockIdx.y * 64;
    int KB0 = blockIdx.z * 128;

    int la  = tid >> 2, lka = (tid & 3) * 8;
    int cb  = tid & 63, lkb = (tid >> 6) * 8;
    const float* Asrc = &g_grid[(A0 + la) * (NC * HH) + KB0 + lka];
    const float* Bsrc = &Wp[(C0 + cb) * (NC * HH) + KB0 + lkb];

    int a0 = (tid >> 4) * 4;
    int c0 = (tid & 15) * 4;

    float4 ra0, ra1, rb0, rb1;
#define K2_LD(c) { const float* sa_ = Asrc + (c) * 32; const float* sb_ = Bsrc + (c) * 32; \
    ra0 = ((const float4*)sa_)[0]; ra1 = ((const float4*)sa_)[1]; \
    rb0 = ((const float4*)sb_)[0]; rb1 = ((const float4*)sb_)[1]; }
#define K2_ST(buf) { \
    *(float4*)&sA[buf][la][lka] = ra0; *(float4*)&sA[buf][la][lka + 4] = ra1; \
    float* b_ = &sB[buf][lkb][cb]; \
    b_[0*64] = rb0.x; b_[1*64] = rb0.y; b_[2*64] = rb0.z; b_[3*64] = rb0.w; \
    b_[4*64] = rb1.x; b_[5*64] = rb1.y; b_[6*64] = rb1.z; b_[7*64] = rb1.w; }

    K2_LD(0); K2_ST(0); K2_LD(1);
    __syncthreads();

    unsigned long long acc[4][2] = {{0ull,0ull},{0ull,0ull},{0ull,0ull},{0ull,0ull}};
    for (int kc = 0; kc < 4; kc++) {
        int cur = kc & 1;
        if (kc + 1 < 4) K2_ST(cur ^ 1);
        if (kc + 2 < 4) K2_LD(kc + 2);
        #pragma unroll
        for (int k = 0; k < 32; k++) {
            ulonglong2 bv = *(const ulonglong2*)&sB[cur][k][c0];
            float x0 = sA[cur][a0 + 0][k];
            float x1 = sA[cur][a0 + 1][k];
            float x2 = sA[cur][a0 + 2][k];
            float x3 = sA[cur][a0 + 3][k];
            unsigned long long xp;
            xp = pack2(x0, x0); acc[0][0] = ffma2(xp, bv.x, acc[0][0]); acc[0][1] = ffma2(xp, bv.y, acc[0][1]);
            xp = pack2(x1, x1); acc[1][0] = ffma2(xp, bv.x, acc[1][0]); acc[1][1] = ffma2(xp, bv.y, acc[1][1]);
            xp = pack2(x2, x2); acc[2][0] = ffma2(xp, bv.x, acc[2][0]); acc[2][1] = ffma2(xp, bv.y, acc[2][1]);
            xp = pack2(x3, x3); acc[3][0] = ffma2(xp, bv.x, acc[3][0]); acc[3][1] = ffma2(xp, bv.y, acc[3][1]);
        }
        __syncthreads();
    }
#undef K2_LD
#undef K2_ST

    float* dst = g_part[blockIdx.z];
    #pragma unroll
    for (int i = 0; i < 4; i++) {
        *(unsigned long long*)&dst[(A0 + a0 + i) * PP + C0 + c0]     = acc[i][0];
        *(unsigned long long*)&dst[(A0 + a0 + i) * PP + C0 + c0 + 2] = acc[i][1];
    }
}

// ---------------- K3: fused x-build + gate GEMM + LSTM pointwise ----------------
// grid(32 agent-tiles, 8 h-tiles) = 256 blocks x 256 thr; 16 agents x 64 gate rows.
__global__ void __launch_bounds__(256) k3_lstm(
    int hbuf, int pos_is_slot, int pos_idx, int prev_idx,
    const float* __restrict__ W_ih, const float* __restrict__ b_ih,
    const float* __restrict__ W_hh, const float* __restrict__ b_hh,
    const float* __restrict__ Wpos, const float* __restrict__ bpos,
    const float* __restrict__ bpool)
{
    __shared__ __align__(16) float sX[KG * 16];          // 20KB (aliased after GEMM)
    __shared__ __align__(16) float sBW[2 * 2 * 8 * 64];  // 8KB [buf][kg][k][row]

    const float* __restrict__ h_in  = g_h[hbuf];
    float*       __restrict__ h_out = g_h[hbuf ^ 1];
    const float* __restrict__ pos  = pos_is_slot ? g_slot[pos_idx]  : (g_obs + pos_idx  * NN * 2);
    const float* __restrict__ prev = pos_is_slot ? g_slot[prev_idx] : (g_obs + prev_idx * NN * 2);

    int tid = threadIdx.x;
    int A0  = blockIdx.x * 16;
    int h0  = blockIdx.y * 16;

    // build x = [relu(vel@Wpos^T+b) | relu(sum(part)+bpool) | h_in]
    for (int it = tid; it < 16 * KG; it += 256) {
        int a = it / KG, k = it - a * KG;
        int ga = A0 + a;
        float v;
        if (k < EE) {
            float vx = pos[ga * 2]     - prev[ga * 2];
            float vy = pos[ga * 2 + 1] - prev[ga * 2 + 1];
            v = fmaxf(Wpos[k * 2] * vx + Wpos[k * 2 + 1] * vy + bpos[k], 0.f);
        } else if (k < KX) {
            int c = k - EE;
            float sum = bpool[c];
            #pragma unroll
            for (int p = 0; p < KSP; p++) sum += g_part[p][ga * PP + c];
            v = fmaxf(sum, 0.f);
        } else {
            v = h_in[ga * HH + (k - KX)];
        }
        sX[k * 16 + a] = v;
    }

    int kg = tid >> 7;          // k-group 0/1 (k in [kg*160, kg*160+160))
    int t  = tid & 127;
    int rr = t & 63;            // gate row within tile (0..63)
    int kh4 = (t >> 6) * 4;     // k sub-offset 0/4
    int grow = h0 + (rr & 15) + ((rr >> 4) * HH);
    const float* ihrow = W_ih + grow * KX;
    const float* hhrow = W_hh + grow * HH;

    float4 w0;
#define L_LD(c) { int kb_ = kg * 160 + (c) * 8 + kh4; \
    const float* s_ = (kb_ < KX) ? (ihrow + kb_) : (hhrow + (kb_ - KX)); \
    w0 = *(const float4*)s_; }
#define L_ST(buf) { float* b_ = &sBW[((buf) * 2 + kg) * 512 + kh4 * 64 + rr]; \
    b_[0*64] = w0.x; b_[1*64] = w0.y; b_[2*64] = w0.z; b_[3*64] = w0.w; }

    L_LD(0); L_ST(0); L_LD(1);
    __syncthreads();

    int ag = t >> 5, rg = t & 31;
    int a0 = ag * 4, r0 = rg * 2;
    unsigned long long acc[4] = {0ull, 0ull, 0ull, 0ull};

    for (int kc = 0; kc < 20; kc++) {
        int cur = kc & 1;
        if (kc + 1 < 20) L_ST(cur ^ 1);
        if (kc + 2 < 20) L_LD(kc + 2);
        int kb = kg * 160 + kc * 8;
        #pragma unroll
        for (int k = 0; k < 8; k++) {
            float4 xv = *(const float4*)&sX[(kb + k) * 16 + a0];
            unsigned long long wv = *(const unsigned long long*)&sBW[(cur * 2 + kg) * 512 + k * 64 + r0];
            acc[0] = ffma2(pack2(xv.x, xv.x), wv, acc[0]);
            acc[1] = ffma2(pack2(xv.y, xv.y), wv, acc[1]);
            acc[2] = ffma2(pack2(xv.z, xv.z), wv, acc[2]);
            acc[3] = ffma2(pack2(xv.w, xv.w), wv, acc[3]);
        }
        __syncthreads();
    }
#undef L_LD
#undef L_ST

    // cross-group reduce + bias + gate staging (alias dead sX region)
    float* sRed = sX;            // [16][64]
    float* sG   = sX + 1024;     // [16][68]

    if (kg == 1) {
        #pragma unroll
        for (int i = 0; i < 4; i++)
            *(unsigned long long*)&sRed[(a0 + i) * 64 + r0] = acc[i];
    }
    __syncthreads();
    if (kg == 0) {
        #pragma unroll
        for (int i = 0; i < 4; i++) {
            float2 pa = upk(acc[i]);
            float2 qa = *(float2*)&sRed[(a0 + i) * 64 + r0];
            float v0 = pa.x + qa.x, v1 = pa.y + qa.y;
            int r = r0;
            int gr0 = h0 + (r & 15) + ((r >> 4) * HH);
            int gr1 = h0 + ((r + 1) & 15) + (((r + 1) >> 4) * HH);
            sG[(a0 + i) * 68 + r]     = v0 + b_ih[gr0] + b_hh[gr0];
            sG[(a0 + i) * 68 + r + 1] = v1 + b_ih[gr1] + b_hh[gr1];
        }
    }
    __syncthreads();

    // LSTM pointwise: 16 agents x 16 channels = 256 threads
    {
        int aa = tid >> 4, hc = tid & 15;
        int ga = A0 + aa;
        float iv = sG[aa * 68 + hc],      fv = sG[aa * 68 + 16 + hc];
        float gv = sG[aa * 68 + 32 + hc], ov = sG[aa * 68 + 48 + hc];
        int idx = ga * HH + h0 + hc;
        float c_old = g_c[idx];
        float si = 1.f / (1.f + __expf(-iv));
        float sf = 1.f / (1.f + __expf(-fv));
        float so = 1.f / (1.f + __expf(-ov));
        float cn = sf * c_old + si * tanhf(gv);
        float hn = so * tanhf(cn);
        g_c[idx]   = cn;
        h_out[idx] = hn;
    }
}

// ---------------- K4: decoder output projection + position advance ----------------
__global__ void __launch_bounds__(256) k4_out(
    int hbuf_new, int s, float* __restrict__ out,
    const float* __restrict__ Wout, const float* __restrict__ bout)
{
    int gid = blockIdx.x * 256 + threadIdx.x;
    int agent = gid >> 1, coord = gid & 1;
    const float* __restrict__ h_new = g_h[hbuf_new];
    const float* __restrict__ pos_cur = g_slot[s & 1];
    float* __restrict__ slot_next = g_slot[(s + 1) & 1];

    const float4* h4 = (const float4*)&h_new[agent * HH];
    const float4* w4 = (const float4*)&Wout[coord * HH];
    float acc = 0.f;
    #pragma unroll
    for (int k = 0; k < HH / 4; k++) {
        float4 a = h4[k], b = w4[k];
        acc += a.x * b.x + a.y * b.y + a.z * b.z + a.w * b.w;
    }
    float v = pos_cur[agent * 2 + coord] + acc + bout[coord];
    slot_next[agent * 2 + coord] = v;
    out[(s * NN + agent) * 2 + coord] = v;
}

// ---------------- host launcher ----------------
extern "C" void kernel_launch(void* const* d_in, const int* in_sizes, int n_in,
                              void* d_out, int out_size) {
    const float* obs   = (const float*)d_in[0];
    const float* Wposw = (const float*)d_in[1];
    const float* bposw = (const float*)d_in[2];
    const float* Wpool = (const float*)d_in[3];
    const float* bpool = (const float*)d_in[4];
    const float* Wihe  = (const float*)d_in[5];
    const float* bihe  = (const float*)d_in[6];
    const float* Whhe  = (const float*)d_in[7];
    const float* bhhe  = (const float*)d_in[8];
    const float* Wihd  = (const float*)d_in[9];
    const float* bihd  = (const float*)d_in[10];
    const float* Whhd  = (const float*)d_in[11];
    const float* bhhd  = (const float*)d_in[12];
    const float* Woutw = (const float*)d_in[13];
    const float* boutw = (const float*)d_in[14];
    float* out = (float*)d_out;
    int np = out_size / (NN * 2);

    k0_setup<<<256, 256>>>(obs);

    int q = 0;
    for (int t = 1; t < TT; t++, q++) {
        int hb = q & 1;
        k1_pool<<<dim3(16, 16), 256>>>(hb, 0, t);
        k2_soc<<<dim3(8, 2, KSP), 256>>>(Wpool);
        k3_lstm<<<dim3(32, 8), 256>>>(hb, 0, t, t - 1,
                                      Wihe, bihe, Whhe, bhhe, Wposw, bposw, bpool);
    }
    for (int s = 0; s < np; s++, q++) {
        int hb = q & 1;
        k1_pool<<<dim3(16, 16), 256>>>(hb, 1, s & 1);
        k2_soc<<<dim3(8, 2, KSP), 256>>>(Wpool);
        k3_lstm<<<dim3(32, 8), 256>>>(hb, 1, s & 1, (s + 1) & 1,
                                      Wihd, bihd, Whhd, bhhd, Wposw, bposw, bpool);
        k4_out<<<4, 256>>>(hb ^ 1, s, out, Woutw, boutw);
    }
    (void)in_sizes; (void)n_in;
}

// round 15
// speedup vs baseline: 1.3131x; 1.0099x over previous
#include <cuda_runtime.h>
#include <math.h>
#include <float.h>

#define TT 8
#define NN 512
#define EE 64
#define HH 128
#define NC 16          // G*G
#define PP 128
#define KX 192         // E + P
#define KG 320         // KX + H
#define KSP 16         // K-splits for soc GEMM

// ---------------- packed f32x2 helpers ----------------
__device__ __forceinline__ unsigned long long ffma2(unsigned long long a,
                                                    unsigned long long b,
                                                    unsigned long long c) {
    unsigned long long d;
    asm("fma.rn.f32x2 %0, %1, %2, %3;" : "=l"(d) : "l"(a), "l"(b), "l"(c));
    return d;
}
__device__ __forceinline__ unsigned long long pack2(float x, float y) {
    unsigned long long d;
    asm("mov.b64 %0, {%1, %2};" : "=l"(d) : "f"(x), "f"(y));
    return d;
}
__device__ __forceinline__ float2 upk(unsigned long long v) {
    float2 f;
    asm("mov.b64 {%0, %1}, %2;" : "=f"(f.x), "=f"(f.y) : "l"(v));
    return f;
}

// ---------------- persistent scratch ----------------
__device__ float g_obs[TT * NN * 2];
__device__ float g_h[2][NN * HH];
__device__ float g_c[NN * HH];
__device__ float g_grid[NN * NC * HH];
__device__ float g_part[KSP][PP * NN];      // [p][channel][agent]
__device__ float g_x[KX * NN];              // [k][agent]: emb | soc
__device__ float g_slot[2][NN * 2];

// ---------------- K0: impute + zero state ----------------
__global__ void k0_setup(const float* __restrict__ obs_in) {
    int gid = blockIdx.x * blockDim.x + threadIdx.x;
    int nth = gridDim.x * blockDim.x;
    for (int i = gid; i < NN * HH; i += nth) {
        g_h[0][i] = 0.f; g_h[1][i] = 0.f; g_c[i] = 0.f;
    }
    if (gid < NN) {
        int n = gid;
        unsigned fm = 0; int first = 0; int ffound = 0;
        for (int t = 0; t < TT; t++) {
            float x = obs_in[(t * NN + n) * 2];
            float y = obs_in[(t * NN + n) * 2 + 1];
            if (isfinite(x) && isfinite(y)) {
                fm |= (1u << t);
                if (!ffound) { first = t; ffound = 1; }
            }
        }
        int last = -1;
        for (int t = 0; t < TT; t++) {
            if (fm & (1u << t)) last = t;
            int take = (last >= 0) ? last : first;
            float wx = 0.f, wy = 0.f;
            if (fm) {
                wx = obs_in[(take * NN + n) * 2];
                wy = obs_in[(take * NN + n) * 2 + 1];
            }
            g_obs[(t * NN + n) * 2]     = wx;
            g_obs[(t * NN + n) * 2 + 1] = wy;
        }
        float sx = g_obs[((TT - 1) * NN + n) * 2];
        float sy = g_obs[((TT - 1) * NN + n) * 2 + 1];
        g_slot[0][n * 2] = sx; g_slot[0][n * 2 + 1] = sy;
        g_slot[1][n * 2] = sx; g_slot[1][n * 2 + 1] = sy;
    }
}

// ---------------- K1: social pooling, channel-split ----------------
// grid(16 agent-groups, 16 ch-groups) x 256 thr; 32 agents x 8 channels per block.
__global__ void __launch_bounds__(256) k1_pool(int hbuf, int pos_is_slot, int pos_idx) {
    __shared__ float spos[NN * 2];                 // 4KB
    __shared__ unsigned char scid[32 * NN];        // 16KB, [a][j]
    __shared__ float htile[64 * 8];                // 2KB
    __shared__ float sg[32 * 136];                 // 17.4KB

    const float* __restrict__ h_in = g_h[hbuf];
    const float* __restrict__ pos  = pos_is_slot ? g_slot[pos_idx] : (g_obs + pos_idx * NN * 2);

    int tid  = threadIdx.x;
    int base = blockIdx.x * 32;
    int ch0  = blockIdx.y * 8;

    for (int i = tid; i < NN * 2; i += 256) spos[i] = pos[i];
    for (int i = tid; i < 32 * 136; i += 256) sg[i] = -FLT_MAX;
    __syncthreads();

    for (int it = tid; it < 32 * NN; it += 256) {
        int a = it >> 9, j = it & (NN - 1);
        int i = base + a;
        float rx = spos[j * 2]     - spos[i * 2];
        float ry = spos[j * 2 + 1] - spos[i * 2 + 1];
        unsigned char cid = 255;
        if (j != i && fabsf(rx) <= 1.0f && fabsf(ry) <= 1.0f) {
            int gx = (int)floorf((rx + 1.0f) * 2.0f);
            int gy = (int)floorf((ry + 1.0f) * 2.0f);
            gx = min(max(gx, 0), 3); gy = min(max(gy, 0), 3);
            cid = (unsigned char)(gx * 4 + gy);
        }
        scid[it] = cid;
    }

    int a  = tid >> 3;          // 0..31
    int ch = tid & 7;           // 0..7
    float* sga = &sg[a * 136];
    const unsigned char* sca = &scid[a * NN];

    for (int jt = 0; jt < NN; jt += 64) {
        __syncthreads();
        for (int i = tid; i < 512; i += 256) {
            int jl = i >> 3, c = i & 7;
            htile[i] = h_in[(jt + jl) * HH + ch0 + c];
        }
        __syncthreads();
        #pragma unroll 4
        for (int j4 = 0; j4 < 16; j4++) {
            uchar4 c4 = *(const uchar4*)&sca[jt + j4 * 4];
            float h0v = htile[(j4 * 4 + 0) * 8 + ch];
            float h1v = htile[(j4 * 4 + 1) * 8 + ch];
            float h2v = htile[(j4 * 4 + 2) * 8 + ch];
            float h3v = htile[(j4 * 4 + 3) * 8 + ch];
            if (c4.x != 255) { float* p = &sga[c4.x * 8 + ch]; *p = fmaxf(*p, h0v); }
            if (c4.y != 255) { float* p = &sga[c4.y * 8 + ch]; *p = fmaxf(*p, h1v); }
            if (c4.z != 255) { float* p = &sga[c4.z * 8 + ch]; *p = fmaxf(*p, h2v); }
            if (c4.w != 255) { float* p = &sga[c4.w * 8 + ch]; *p = fmaxf(*p, h3v); }
        }
    }
    __syncthreads();

    for (int it = tid; it < 32 * 128; it += 256) {
        int aa = it >> 7, rest = it & 127;
        int cell = rest >> 3, c = rest & 7;
        float v = sg[aa * 136 + cell * 8 + c];
        g_grid[(base + aa) * (NC * HH) + cell * HH + ch0 + c] = (v == -FLT_MAX) ? 0.f : v;
    }
}

// ---------------- K2: soc GEMM partials (transposed [c][agent] output) ----------------
// grid(8 M, 2 N, 16 Ksplit) = 256 blocks x 256 thr; tile 64x64, K=128/split.
__global__ void __launch_bounds__(256) k2_soc(const float* __restrict__ Wp) {
    __shared__ __align__(16) float sA[2][64][36];
    __shared__ __align__(16) float sB[2][32][64];

    int tid = threadIdx.x;
    int A0  = blockIdx.x * 64;
    int C0  = blockIdx.y * 64;
    int KB0 = blockIdx.z * 128;

    int la  = tid >> 2, lka = (tid & 3) * 8;
    int cb  = tid & 63, lkb = (tid >> 6) * 8;
    const float* Asrc = &g_grid[(A0 + la) * (NC * HH) + KB0 + lka];
    const float* Bsrc = &Wp[(C0 + cb) * (NC * HH) + KB0 + lkb];

    int a0 = (tid >> 4) * 4;
    int c0 = (tid & 15) * 4;

    float4 ra0, ra1, rb0, rb1;
#define K2_LD(c) { const float* sa_ = Asrc + (c) * 32; const float* sb_ = Bsrc + (c) * 32; \
    ra0 = ((const float4*)sa_)[0]; ra1 = ((const float4*)sa_)[1]; \
    rb0 = ((const float4*)sb_)[0]; rb1 = ((const float4*)sb_)[1]; }
#define K2_ST(buf) { \
    *(float4*)&sA[buf][la][lka] = ra0; *(float4*)&sA[buf][la][lka + 4] = ra1; \
    float* b_ = &sB[buf][lkb][cb]; \
    b_[0*64] = rb0.x; b_[1*64] = rb0.y; b_[2*64] = rb0.z; b_[3*64] = rb0.w; \
    b_[4*64] = rb1.x; b_[5*64] = rb1.y; b_[6*64] = rb1.z; b_[7*64] = rb1.w; }

    K2_LD(0); K2_ST(0); K2_LD(1);
    __syncthreads();

    unsigned long long acc[4][2] = {{0ull,0ull},{0ull,0ull},{0ull,0ull},{0ull,0ull}};
    for (int kc = 0; kc < 4; kc++) {
        int cur = kc & 1;
        if (kc + 1 < 4) K2_ST(cur ^ 1);
        if (kc + 2 < 4) K2_LD(kc + 2);
        #pragma unroll
        for (int k = 0; k < 32; k++) {
            ulonglong2 bv = *(const ulonglong2*)&sB[cur][k][c0];
            float x0 = sA[cur][a0 + 0][k];
            float x1 = sA[cur][a0 + 1][k];
            float x2 = sA[cur][a0 + 2][k];
            float x3 = sA[cur][a0 + 3][k];
            unsigned long long xp;
            xp = pack2(x0, x0); acc[0][0] = ffma2(xp, bv.x, acc[0][0]); acc[0][1] = ffma2(xp, bv.y, acc[0][1]);
            xp = pack2(x1, x1); acc[1][0] = ffma2(xp, bv.x, acc[1][0]); acc[1][1] = ffma2(xp, bv.y, acc[1][1]);
            xp = pack2(x2, x2); acc[2][0] = ffma2(xp, bv.x, acc[2][0]); acc[2][1] = ffma2(xp, bv.y, acc[2][1]);
            xp = pack2(x3, x3); acc[3][0] = ffma2(xp, bv.x, acc[3][0]); acc[3][1] = ffma2(xp, bv.y, acc[3][1]);
        }
        __syncthreads();
    }
#undef K2_LD
#undef K2_ST

    // transposed store: [channel][agent]
    float va[4][4];
    #pragma unroll
    for (int i = 0; i < 4; i++) {
        float2 p01 = upk(acc[i][0]), p23 = upk(acc[i][1]);
        va[i][0] = p01.x; va[i][1] = p01.y; va[i][2] = p23.x; va[i][3] = p23.y;
    }
    float* dst = g_part[blockIdx.z];
    #pragma unroll
    for (int q = 0; q < 4; q++) {
        float4 v = make_float4(va[0][q], va[1][q], va[2][q], va[3][q]);
        *(float4*)&dst[(C0 + c0 + q) * NN + A0 + a0] = v;
    }
}

// ---------------- K2X: build x-prefix g_x[192][512] = [emb | soc] ----------------
// 384 blocks x 256 thr; 1 element/thread; all loads coalesced over agent.
__global__ void __launch_bounds__(256) k2x_build(
    int pos_is_slot, int pos_idx, int prev_idx,
    const float* __restrict__ Wpos, const float* __restrict__ bpos,
    const float* __restrict__ bpool)
{
    const float* __restrict__ pos  = pos_is_slot ? g_slot[pos_idx]  : (g_obs + pos_idx  * NN * 2);
    const float* __restrict__ prev = pos_is_slot ? g_slot[prev_idx] : (g_obs + prev_idx * NN * 2);

    int gid = blockIdx.x * 256 + threadIdx.x;   // 0 .. KX*NN-1
    int k = gid >> 9, agent = gid & (NN - 1);
    float v;
    if (k < EE) {
        float vx = pos[agent * 2]     - prev[agent * 2];
        float vy = pos[agent * 2 + 1] - prev[agent * 2 + 1];
        v = fmaxf(Wpos[k * 2] * vx + Wpos[k * 2 + 1] * vy + bpos[k], 0.f);
    } else {
        int c = k - EE;
        float sum = bpool[c];
        #pragma unroll
        for (int p = 0; p < KSP; p++) sum += g_part[p][c * NN + agent];
        v = fmaxf(sum, 0.f);
    }
    g_x[k * NN + agent] = v;
}

// ---------------- K3: gate GEMM + LSTM pointwise ----------------
// grid(32 agent-tiles, 8 h-tiles) = 256 blocks x 256 thr; 16 agents x 64 gate rows.
__global__ void __launch_bounds__(256) k3_lstm(
    int hbuf,
    const float* __restrict__ W_ih, const float* __restrict__ b_ih,
    const float* __restrict__ W_hh, const float* __restrict__ b_hh)
{
    __shared__ __align__(16) float sX[KG * 16];          // 20KB (aliased after GEMM)
    __shared__ __align__(16) float sBW[2 * 2 * 8 * 64];  // 8KB [buf][kg][k][row]

    const float* __restrict__ h_in  = g_h[hbuf];
    float*       __restrict__ h_out = g_h[hbuf ^ 1];

    int tid = threadIdx.x;
    int A0  = blockIdx.x * 16;
    int h0  = blockIdx.y * 16;

    // x-build: coalesced copies (g_x rows, then h rows transposed)
    for (int it = tid; it < 16 * KX; it += 256) {
        int a = it & 15, k = it >> 4;
        sX[k * 16 + a] = g_x[k * NN + A0 + a];
    }
    for (int it = tid; it < 16 * HH; it += 256) {
        int a = it >> 7, ch = it & 127;
        sX[(KX + ch) * 16 + a] = h_in[(A0 + a) * HH + ch];
    }

    int kg = tid >> 7;          // k-group 0/1
    int t  = tid & 127;
    int rr = t & 63;            // gate row within tile (0..63)
    int kh4 = (t >> 6) * 4;     // k sub-offset 0/4
    int grow = h0 + (rr & 15) + ((rr >> 4) * HH);
    const float* ihrow = W_ih + grow * KX;
    const float* hhrow = W_hh + grow * HH;

    float4 w0;
#define L_LD(c) { int kb_ = kg * 160 + (c) * 8 + kh4; \
    const float* s_ = (kb_ < KX) ? (ihrow + kb_) : (hhrow + (kb_ - KX)); \
    w0 = *(const float4*)s_; }
#define L_ST(buf) { float* b_ = &sBW[((buf) * 2 + kg) * 512 + kh4 * 64 + rr]; \
    b_[0*64] = w0.x; b_[1*64] = w0.y; b_[2*64] = w0.z; b_[3*64] = w0.w; }

    L_LD(0); L_ST(0); L_LD(1);
    __syncthreads();

    int ag = t >> 5, rg = t & 31;
    int a0 = ag * 4, r0 = rg * 2;
    unsigned long long acc[4] = {0ull, 0ull, 0ull, 0ull};

    for (int kc = 0; kc < 20; kc++) {
        int cur = kc & 1;
        if (kc + 1 < 20) L_ST(cur ^ 1);
        if (kc + 2 < 20) L_LD(kc + 2);
        int kb = kg * 160 + kc * 8;
        #pragma unroll
        for (int k = 0; k < 8; k++) {
            float4 xv = *(const float4*)&sX[(kb + k) * 16 + a0];
            unsigned long long wv = *(const unsigned long long*)&sBW[(cur * 2 + kg) * 512 + k * 64 + r0];
            acc[0] = ffma2(pack2(xv.x, xv.x), wv, acc[0]);
            acc[1] = ffma2(pack2(xv.y, xv.y), wv, acc[1]);
            acc[2] = ffma2(pack2(xv.z, xv.z), wv, acc[2]);
            acc[3] = ffma2(pack2(xv.w, xv.w), wv, acc[3]);
        }
        __syncthreads();
    }
#undef L_LD
#undef L_ST

    // cross-group reduce + bias + gate staging (alias dead sX region)
    float* sRed = sX;            // [16][64]
    float* sG   = sX + 1024;     // [16][68]

    if (kg == 1) {
        #pragma unroll
        for (int i = 0; i < 4; i++)
            *(unsigned long long*)&sRed[(a0 + i) * 64 + r0] = acc[i];
    }
    __syncthreads();
    if (kg == 0) {
        #pragma unroll
        for (int i = 0; i < 4; i++) {
            float2 pa = upk(acc[i]);
            float2 qa = *(float2*)&sRed[(a0 + i) * 64 + r0];
            float v0 = pa.x + qa.x, v1 = pa.y + qa.y;
            int r = r0;
            int gr0 = h0 + (r & 15) + ((r >> 4) * HH);
            int gr1 = h0 + ((r + 1) & 15) + (((r + 1) >> 4) * HH);
            sG[(a0 + i) * 68 + r]     = v0 + b_ih[gr0] + b_hh[gr0];
            sG[(a0 + i) * 68 + r + 1] = v1 + b_ih[gr1] + b_hh[gr1];
        }
    }
    __syncthreads();

    // LSTM pointwise: 16 agents x 16 channels = 256 threads
    {
        int aa = tid >> 4, hc = tid & 15;
        int ga = A0 + aa;
        float iv = sG[aa * 68 + hc],      fv = sG[aa * 68 + 16 + hc];
        float gv = sG[aa * 68 + 32 + hc], ov = sG[aa * 68 + 48 + hc];
        int idx = ga * HH + h0 + hc;
        float c_old = g_c[idx];
        float si = 1.f / (1.f + __expf(-iv));
        float sf = 1.f / (1.f + __expf(-fv));
        float so = 1.f / (1.f + __expf(-ov));
        float cn = sf * c_old + si * tanhf(gv);
        float hn = so * tanhf(cn);
        g_c[idx]   = cn;
        h_out[idx] = hn;
    }
}

// ---------------- K4: decoder output projection + position advance ----------------
__global__ void __launch_bounds__(256) k4_out(
    int hbuf_new, int s, float* __restrict__ out,
    const float* __restrict__ Wout, const float* __restrict__ bout)
{
    int gid = blockIdx.x * 256 + threadIdx.x;
    int agent = gid >> 1, coord = gid & 1;
    const float* __restrict__ h_new = g_h[hbuf_new];
    const float* __restrict__ pos_cur = g_slot[s & 1];
    float* __restrict__ slot_next = g_slot[(s + 1) & 1];

    const float4* h4 = (const float4*)&h_new[agent * HH];
    const float4* w4 = (const float4*)&Wout[coord * HH];
    float acc = 0.f;
    #pragma unroll
    for (int k = 0; k < HH / 4; k++) {
        float4 a = h4[k], b = w4[k];
        acc += a.x * b.x + a.y * b.y + a.z * b.z + a.w * b.w;
    }
    float v = pos_cur[agent * 2 + coord] + acc + bout[coord];
    slot_next[agent * 2 + coord] = v;
    out[(s * NN + agent) * 2 + coord] = v;
}

// ---------------- host launcher ----------------
extern "C" void kernel_launch(void* const* d_in, const int* in_sizes, int n_in,
                              void* d_out, int out_size) {
    const float* obs   = (const float*)d_in[0];
    const float* Wposw = (const float*)d_in[1];
    const float* bposw = (const float*)d_in[2];
    const float* Wpool = (const float*)d_in[3];
    const float* bpool = (const float*)d_in[4];
    const float* Wihe  = (const float*)d_in[5];
    const float* bihe  = (const float*)d_in[6];
    const float* Whhe  = (const float*)d_in[7];
    const float* bhhe  = (const float*)d_in[8];
    const float* Wihd  = (const float*)d_in[9];
    const float* bihd  = (const float*)d_in[10];
    const float* Whhd  = (const float*)d_in[11];
    const float* bhhd  = (const float*)d_in[12];
    const float* Woutw = (const float*)d_in[13];
    const float* boutw = (const float*)d_in[14];
    float* out = (float*)d_out;
    int np = out_size / (NN * 2);

    k0_setup<<<256, 256>>>(obs);

    int q = 0;
    for (int t = 1; t < TT; t++, q++) {
        int hb = q & 1;
        k1_pool<<<dim3(16, 16), 256>>>(hb, 0, t);
        k2_soc<<<dim3(8, 2, KSP), 256>>>(Wpool);
        k2x_build<<<(KX * NN) / 256, 256>>>(0, t, t - 1, Wposw, bposw, bpool);
        k3_lstm<<<dim3(32, 8), 256>>>(hb, Wihe, bihe, Whhe, bhhe);
    }
    for (int s = 0; s < np; s++, q++) {
        int hb = q & 1;
        k1_pool<<<dim3(16, 16), 256>>>(hb, 1, s & 1);
        k2_soc<<<dim3(8, 2, KSP), 256>>>(Wpool);
        k2x_build<<<(KX * NN) / 256, 256>>>(1, s & 1, (s + 1) & 1, Wposw, bposw, bpool);
        k3_lstm<<<dim3(32, 8), 256>>>(hb, Wihd, bihd, Whhd, bhhd);
        k4_out<<<4, 256>>>(hb ^ 1, s, out, Woutw, boutw);
    }
    (void)in_sizes; (void)n_in;
}